// round 14
// baseline (speedup 1.0000x reference)
#include <cuda_runtime.h>
#include <cstdint>

#define LQ 512
#define HID 400
#define GATES 1600
#define CLUST 16
#define UPC 25
#define THREADS 416       // 13 warps

// ---------------- scratch ----------------
__device__ float g_x0[LQ * 400];
__device__ float g_xp[2 * LQ * CLUST * 112];   // permuted xi: [dir][t][rank][112]
__device__ float g_H0[LQ * 800];
__device__ float g_H1[LQ * 800];
__device__ float g_sv[LQ], g_tv[LQ];

// ---------------- helpers ----------------
__device__ __forceinline__ unsigned long long pk2(float lo, float hi) {
    unsigned long long r; asm("mov.b64 %0,{%1,%2};" : "=l"(r) : "f"(lo), "f"(hi)); return r;
}
__device__ __forceinline__ void upk2(unsigned long long v, float& lo, float& hi) {
    asm("mov.b64 {%0,%1},%2;" : "=f"(lo), "=f"(hi) : "l"(v));
}
__device__ __forceinline__ void fma2(unsigned long long& d, unsigned long long a, unsigned long long b) {
    asm("fma.rn.f32x2 %0,%1,%2,%3;" : "=l"(d) : "l"(a), "l"(b), "l"(d));
}
__device__ __forceinline__ unsigned s2u(const void* p) {
    unsigned a; asm("{ .reg .u64 t; cvta.to.shared.u64 t, %1; cvt.u32.u64 %0, t; }" : "=r"(a) : "l"(p)); return a;
}
__device__ __forceinline__ unsigned mapa_u(unsigned a, unsigned r) {
    unsigned o; asm("mapa.shared::cluster.u32 %0, %1, %2;" : "=r"(o) : "r"(a), "r"(r)); return o;
}
__device__ __forceinline__ void mbar_init(unsigned a, unsigned c) {
    asm volatile("mbarrier.init.shared.b64 [%0], %1;" :: "r"(a), "r"(c) : "memory");
}
__device__ __forceinline__ void mbar_wait_clu(unsigned a, unsigned ph) {
    asm volatile(
        "{\n\t.reg .pred P;\n"
        "W%=:\n\tmbarrier.try_wait.parity.acquire.cluster.shared::cta.b64 P, [%0], %1, 0x989680;\n"
        "\t@P bra D%=;\n\tbra W%=;\nD%=:\n\t}"
        :: "r"(a), "r"(ph) : "memory");
}
// RELAXED remote arrive: wake hint; tags carry data validity
__device__ __forceinline__ void mbar_arrive_rlx(unsigned a) {
    asm volatile("mbarrier.arrive.relaxed.cluster.shared::cluster.b64 _, [%0];" :: "r"(a) : "memory");
}
__device__ __forceinline__ void lds128(uint4& q, unsigned a) {
    asm volatile("ld.shared.v4.u32 {%0,%1,%2,%3}, [%4];"
                 : "=r"(q.x), "=r"(q.y), "=r"(q.z), "=r"(q.w) : "r"(a));
}

// ---------------- dummy (profiling slot alignment) ----------------
__global__ void dummy_k() {}

// ---------------- embedding gather ----------------
__global__ void embed_k(const int* __restrict__ wi, const int* __restrict__ ti,
                        const float* __restrict__ we, const float* __restrict__ te)
{
    int t = blockIdx.x, tid = threadIdx.x;
    const float* wr = we + (size_t)wi[t] * 300;
    for (int k = tid; k < 300; k += 128) g_x0[t * 400 + k] = wr[k];
    const float* tr = te + (size_t)ti[t] * 100;
    if (tid < 100) g_x0[t * 400 + 300 + tid] = tr[tid];
}

// ---------------- xi GEMM: k-major smem, vectorized inner loads ----------------
__global__ void __launch_bounds__(256) gemm_k(int layer,
        const float* __restrict__ W, const float* __restrict__ bih, const float* __restrict__ bhh)
{
    const int K = layer ? 800 : 400;
    const float* A = layer ? g_H0 : g_x0;
    int dir = blockIdx.z;
    int n0 = blockIdx.x * 64, m0 = blockIdx.y * 64;
    const float* Bp = W + (size_t)dir * GATES * K;

    __shared__ float As[16][72];
    __shared__ float Bs[16][72];
    int tid = threadIdx.x;
    int lr = tid >> 2, lc = (tid & 3) * 4;
    int tx = tid & 15, ty = tid >> 4;
    float acc[4][4] = {};

    for (int kt = 0; kt < K; kt += 16) {
        float4 av = *(const float4*)(A + (size_t)(m0 + lr) * K + kt + lc);
        float4 bv = *(const float4*)(Bp + (size_t)(n0 + lr) * K + kt + lc);
        __syncthreads();
        As[lc + 0][lr] = av.x; As[lc + 1][lr] = av.y; As[lc + 2][lr] = av.z; As[lc + 3][lr] = av.w;
        Bs[lc + 0][lr] = bv.x; Bs[lc + 1][lr] = bv.y; Bs[lc + 2][lr] = bv.z; Bs[lc + 3][lr] = bv.w;
        __syncthreads();
#pragma unroll
        for (int kk = 0; kk < 16; ++kk) {
            float4 a4 = *(const float4*)&As[kk][ty * 4];
            float4 b4 = *(const float4*)&Bs[kk][tx * 4];
            acc[0][0] += a4.x * b4.x; acc[0][1] += a4.x * b4.y;
            acc[0][2] += a4.x * b4.z; acc[0][3] += a4.x * b4.w;
            acc[1][0] += a4.y * b4.x; acc[1][1] += a4.y * b4.y;
            acc[1][2] += a4.y * b4.z; acc[1][3] += a4.y * b4.w;
            acc[2][0] += a4.z * b4.x; acc[2][1] += a4.z * b4.y;
            acc[2][2] += a4.z * b4.z; acc[2][3] += a4.z * b4.w;
            acc[3][0] += a4.w * b4.x; acc[3][1] += a4.w * b4.y;
            acc[3][2] += a4.w * b4.z; acc[3][3] += a4.w * b4.w;
        }
    }
#pragma unroll
    for (int jj = 0; jj < 4; ++jj) {
        int n = n0 + tx * 4 + jj;
        float bias = bih[dir * GATES + n] + bhh[dir * GATES + n];
        int gate = n / 400;
        int unit = n - gate * 400;
        int r2 = unit / 25, uw = unit % 25;
        int wp = uw >> 1, un = uw & 1;
        int jq = un * 4 + gate;
#pragma unroll
        for (int i = 0; i < 4; ++i) {
            int m = m0 + ty * 4 + i;
            size_t o = (((size_t)(dir * LQ + m)) * CLUST + r2) * 112 + wp * 8 + jq;
            g_xp[o] = acc[i][jj] + bias;
        }
    }
}

// ---------------- cluster LSTM scan: tagged atoms + progress-ledger arrives ----------------
__global__ void __launch_bounds__(THREADS, 1) __cluster_dims__(CLUST, 1, 1)
scan_k(int layer, const float* __restrict__ Whh)
{
    // h_tag[parity 2][rank 16][slot 28] : u64 = {lo: f32 h, hi: u32 tag}
    __shared__ __align__(16) unsigned long long h_tag[2 * 448];
    __shared__ __align__(8)  unsigned long long mb[2];   // full0 full1 (count 16 each)
    __shared__ __align__(16) unsigned wstep[16];          // per-warp progress ledger

    int dir = blockIdx.x >> 4;
    unsigned rank; asm("mov.u32 %0, %%cluster_ctarank;" : "=r"(rank));
    int w = threadIdx.x >> 5, ld = threadIdx.x & 31;

    unsigned hb = s2u(h_tag), mbb = s2u(mb), wsb = s2u(wstep);

    if (threadIdx.x == 0) { mbar_init(mbb + 0, 16); mbar_init(mbb + 8, 16); }
    if (threadIdx.x < 16) wstep[threadIdx.x] = 0u;
    for (int i = threadIdx.x; i < 2 * 448; i += THREADS) {
        int q = i % 28;
        h_tag[i] = (q >= UPC) ? 0xFFFFFFFF00000000ULL : 0ULL;   // pads always pass
    }

    // ---- register-resident recurrent weights, mapped to PADDED (28/rank) slot layout ----
    unsigned long long wt[2][4][7];
    int uA = 2 * w, uB = 2 * w + 1;
    bool vB = (uB < UPC);
    int guA = rank * UPC + uA;
    int guB = rank * UPC + (vB ? uB : uA);
#pragma unroll
    for (int u = 0; u < 2; ++u) {
        bool vu = u ? vB : true;
        int gu = u ? guB : guA;
#pragma unroll
        for (int g = 0; g < 4; ++g) {
            const float* row = Whh + ((size_t)(dir * GATES + g * HID + gu)) * HID;
#pragma unroll
            for (int kk = 0; kk < 7; ++kk) {
                int m = 2 * ld + 64 * kk;
                int r = m / 28, q = m % 28;
                float lo = 0.f, hi = 0.f;
                if (vu && q < UPC)     lo = row[r * UPC + q];
                if (vu && q + 1 < UPC) hi = row[r * UPC + q + 1];
                wt[u][g][kk] = pk2(lo, hi);
            }
        }
    }

    // ---- per-lane remote store address: lane -> dst rank ld>>1, own unit lu=2w+(ld&1) ----
    int usel = ld & 1;
    int lu = 2 * w + usel;
    bool st_valid = (lu < UPC);
    unsigned st_base = mapa_u(hb, (unsigned)(ld >> 1)) + (unsigned)((rank * 28 + lu) * 8);

    // ---- warp0 remote arrive addresses: lane ld<16 -> rank ld ----
    unsigned rmb = mapa_u(mbb, (unsigned)(ld & 15));

    // ---- warp0 ledger poll address (lane ld reads wstep[min(ld,12)]) ----
    unsigned wsaddr = wsb + (unsigned)((ld < 13 ? ld : 12) * 4);

    // ---- xi pointer: lane value j = (ld>>2)&7 ----
    int j = (ld >> 2) & 7;
    const float* xptr = g_xp + ((size_t)dir * LQ * CLUST + rank) * 112 + w * 8 + j;

    float* Hout = layer ? g_H1 : g_H0;
    float cA = 0.f, cB = 0.f;
    bool b4 = (ld & 16), b3 = (ld & 8), b2 = (ld & 4);
    unsigned ph0 = 0, ph1 = 0;

    asm volatile("barrier.cluster.arrive.aligned;" ::: "memory");
    asm volatile("barrier.cluster.wait.aligned;"  ::: "memory");

    for (int s = 0; s < LQ; ++s) {
        int t = dir ? (LQ - 1 - s) : s;
        float xig = __ldg(xptr + (size_t)t * (CLUST * 112));
        int b = s & 1;

        float v[8];
        if (s > 0) {
            int bp = b ^ 1;                       // buffer holding h_{s-1}
            if (bp) { mbar_wait_clu(mbb + 8, ph1); ph1 ^= 1; }
            else    { mbar_wait_clu(mbb + 0, ph0); ph0 ^= 1; }

            // load {h,tag} pairs; tags carry data validity (exactly s before our own publish)
            unsigned rbase = hb + (unsigned)(bp * 3584 + ld * 16);
            unsigned tgt = (unsigned)s;
            uint4 q0, q1, q2, q3, q4, q5, q6;
            for (;;) {
                lds128(q0, rbase);
                lds128(q1, rbase + 512);
                lds128(q2, rbase + 1024);
                lds128(q3, rbase + 1536);
                lds128(q4, rbase + 2048);
                lds128(q5, rbase + 2560);
                lds128(q6, rbase + 3072);
                bool ok = (q0.y >= tgt) & (q0.w >= tgt) & (q1.y >= tgt) & (q1.w >= tgt)
                        & (q2.y >= tgt) & (q2.w >= tgt) & (q3.y >= tgt) & (q3.w >= tgt)
                        & (q4.y >= tgt) & (q4.w >= tgt) & (q5.y >= tgt) & (q5.w >= tgt)
                        & (q6.y >= tgt) & (q6.w >= tgt);
                if (ok) break;
            }

            unsigned long long acc[2][4] = {};
#pragma unroll
            for (int kk = 0; kk < 7; ++kk) {
                uint4 qq = (kk == 0) ? q0 : (kk == 1) ? q1 : (kk == 2) ? q2 :
                           (kk == 3) ? q3 : (kk == 4) ? q4 : (kk == 5) ? q5 : q6;
                unsigned long long hv = pk2(__uint_as_float(qq.x), __uint_as_float(qq.z));
                fma2(acc[0][0], wt[0][0][kk], hv);
                fma2(acc[0][1], wt[0][1][kk], hv);
                fma2(acc[0][2], wt[0][2][kk], hv);
                fma2(acc[0][3], wt[0][3][kk], hv);
                fma2(acc[1][0], wt[1][0][kk], hv);
                fma2(acc[1][1], wt[1][1][kk], hv);
                fma2(acc[1][2], wt[1][2][kk], hv);
                fma2(acc[1][3], wt[1][3][kk], hv);
            }
#pragma unroll
            for (int u = 0; u < 2; ++u)
#pragma unroll
                for (int g = 0; g < 4; ++g) {
                    float lo, hi; upk2(acc[u][g], lo, hi);
                    v[u * 4 + g] = lo + hi;
                }
        } else {
#pragma unroll
            for (int q = 0; q < 8; ++q) v[q] = 0.f;
        }

        // value-merging butterfly: value j lands in lanes with (ld>>2)&7 == j
        float wv[4];
#pragma unroll
        for (int k = 0; k < 4; ++k) {
            float keep = b4 ? v[k + 4] : v[k];
            float send = b4 ? v[k] : v[k + 4];
            wv[k] = keep + __shfl_xor_sync(0xffffffffu, send, 16);
        }
        float uv[2];
#pragma unroll
        for (int k = 0; k < 2; ++k) {
            float keep = b3 ? wv[k + 2] : wv[k];
            float send = b3 ? wv[k] : wv[k + 2];
            uv[k] = keep + __shfl_xor_sync(0xffffffffu, send, 8);
        }
        float z;
        {
            float keep = b2 ? uv[1] : uv[0];
            float send = b2 ? uv[0] : uv[1];
            z = keep + __shfl_xor_sync(0xffffffffu, send, 4);
        }
        z += __shfl_xor_sync(0xffffffffu, z, 2);
        z += __shfl_xor_sync(0xffffffffu, z, 1);

        // lane-parallel nonlinearity
        int gate = j & 3;
        float x = z + xig;
        float sarg = (gate == 2) ? 2.f * x : x;
        float e = __expf(-sarg);
        float rr = __fdividef(1.f, 1.f + e);
        float y = (gate == 2) ? (2.f * rr - 1.f) : rr;

        float iA = __shfl_sync(0xffffffffu, y, 0);
        float fA = __shfl_sync(0xffffffffu, y, 4);
        float gA = __shfl_sync(0xffffffffu, y, 8);
        float oA = __shfl_sync(0xffffffffu, y, 12);
        float iB = __shfl_sync(0xffffffffu, y, 16);
        float fB = __shfl_sync(0xffffffffu, y, 20);
        float gB = __shfl_sync(0xffffffffu, y, 24);
        float oB = __shfl_sync(0xffffffffu, y, 28);
        cA = fA * cA + iA * gA;
        cB = fB * cB + iB * gB;

        float xc = usel ? cB : cA;
        float ec = __expf(-2.f * xc);
        float tc = __fdividef(2.f, 1.f + ec) - 1.f;
        float tA = __shfl_sync(0xffffffffu, tc, 0);
        float tB = __shfl_sync(0xffffffffu, tc, 1);
        float hA = oA * tA, hB = oB * tB;

        // gmem h output (R4 ordering: before broadcast)
        if (ld == 0) {
            float* o = Hout + (size_t)t * 800 + dir * HID;
            o[guA] = hA;
            if (vB) o[guB] = hB;
        }

        if (s < LQ - 1) {
            // broadcast {h, tag=s+1} atoms via per-lane scattered remote stores
            if (st_valid) {
                unsigned long long pay = ((unsigned long long)(unsigned)(s + 1) << 32) |
                                         (unsigned long long)__float_as_uint(usel ? hB : hA);
                asm volatile("st.shared::cluster.u64 [%0], %1;"
                             :: "r"(st_base + (unsigned)(b * 3584)), "l"(pay) : "memory");
            }
            // publish this warp's progress (reads of buffer b^1 provably complete:
            // the gate math consumed them). Non-zero lanes continue immediately.
            if (ld == 0)
                asm volatile("st.volatile.shared.u32 [%0], %1;"
                             :: "r"(wsb + (unsigned)(w * 4)), "r"((unsigned)(s + 1)) : "memory");
            // warp 0: wait for ALL 13 warps' ledgers, then fire wake arrives.
            // This certifies whole-CTA completion of step s -> WAR-safe for writers of s+1.
            if (w == 0) {
                unsigned f;
                do {
                    asm volatile("ld.volatile.shared.u32 %0, [%1];" : "=r"(f) : "r"(wsaddr));
                } while (!__all_sync(0xffffffffu, f >= (unsigned)(s + 1)));
                if (ld < 16) mbar_arrive_rlx(rmb + (unsigned)(b * 8));
            }
        }
    }

    asm volatile("barrier.cluster.arrive.aligned;" ::: "memory");
    asm volatile("barrier.cluster.wait.aligned;"  ::: "memory");
}

// ---------------- head/dep projections ----------------
__global__ void headdep_k(const float* __restrict__ fw)
{
    int i = blockIdx.x;
    const float* hr = g_H1 + (size_t)i * 800;
    float a = 0.f, b = 0.f;
    for (int k = threadIdx.x; k < 800; k += 256) {
        float h = hr[k];
        a += h * __ldg(fw + k);
        b += h * __ldg(fw + 800 + k);
    }
#pragma unroll
    for (int o = 16; o; o >>= 1) {
        a += __shfl_xor_sync(0xffffffffu, a, o);
        b += __shfl_xor_sync(0xffffffffu, b, o);
    }
    __shared__ float sa[8], sb2[8];
    int w = threadIdx.x >> 5, ld = threadIdx.x & 31;
    if (ld == 0) { sa[w] = a; sb2[w] = b; }
    __syncthreads();
    if (threadIdx.x == 0) {
        float A = 0.f, B = 0.f;
#pragma unroll
        for (int q = 0; q < 8; ++q) { A += sa[q]; B += sb2[q]; }
        g_sv[i] = A; g_tv[i] = B;
    }
}

// ---------------- pairwise scores ----------------
__global__ void scores_k(const float* __restrict__ fb, float* __restrict__ out)
{
    int i = blockIdx.x, jj = threadIdx.x;
    out[(size_t)i * LQ + jj] = tanhf(g_sv[i] + g_tv[jj] + fb[0]);
}

// ---------------- launch ----------------
extern "C" void kernel_launch(void* const* d_in, const int* in_sizes, int n_in,
                              void* d_out, int out_size)
{
    int base = (in_sizes[2] == 1) ? 3 : 2;
    const int*   wi   = (const int*)d_in[0];
    const int*   ti   = (const int*)d_in[1];
    const float* we   = (const float*)d_in[base + 0];
    const float* te   = (const float*)d_in[base + 1];
    const float* wih0 = (const float*)d_in[base + 2];
    const float* whh0 = (const float*)d_in[base + 3];
    const float* bih0 = (const float*)d_in[base + 4];
    const float* bhh0 = (const float*)d_in[base + 5];
    const float* wih1 = (const float*)d_in[base + 6];
    const float* whh1 = (const float*)d_in[base + 7];
    const float* bih1 = (const float*)d_in[base + 8];
    const float* bhh1 = (const float*)d_in[base + 9];
    const float* fw   = (const float*)d_in[base + 10];
    const float* fb   = (const float*)d_in[base + 11];
    float* out = (float*)d_out;

    cudaFuncSetAttribute(scan_k, cudaFuncAttributeNonPortableClusterSizeAllowed, 1);

    embed_k<<<LQ, 128>>>(wi, ti, we, te);
    dim3 gg(GATES / 64, LQ / 64, 2);
    gemm_k<<<gg, 256>>>(0, wih0, bih0, bhh0);
    dummy_k<<<1, 32>>>();                          // keeps scan_k at ncu capture slot 5
    scan_k<<<2 * CLUST, THREADS>>>(0, whh0);
    gemm_k<<<gg, 256>>>(1, wih1, bih1, bhh1);
    scan_k<<<2 * CLUST, THREADS>>>(1, whh1);
    headdep_k<<<LQ, 256>>>(fw);
    scores_k<<<LQ, LQ>>>(fb, out);
}

// round 17
// speedup vs baseline: 1.2371x; 1.2371x over previous
#include <cuda_runtime.h>
#include <cstdint>

#define LQ 512
#define HID 400
#define GATES 1600
#define CLUST 16
#define UPC 25
#define THREADS 416       // 13 warps

// ---------------- scratch ----------------
__device__ float g_x0[LQ * 400];
__device__ float g_xp[2 * LQ * CLUST * 112];   // permuted xi: [dir][t][rank][112]
__device__ float g_H0[LQ * 800];
__device__ float g_H1[LQ * 800];
__device__ float g_sv[LQ], g_tv[LQ];

// ---------------- helpers ----------------
__device__ __forceinline__ unsigned long long pk2(float lo, float hi) {
    unsigned long long r; asm("mov.b64 %0,{%1,%2};" : "=l"(r) : "f"(lo), "f"(hi)); return r;
}
__device__ __forceinline__ void upk2(unsigned long long v, float& lo, float& hi) {
    asm("mov.b64 {%0,%1},%2;" : "=f"(lo), "=f"(hi) : "l"(v));
}
__device__ __forceinline__ void fma2(unsigned long long& d, unsigned long long a, unsigned long long b) {
    asm("fma.rn.f32x2 %0,%1,%2,%3;" : "=l"(d) : "l"(a), "l"(b), "l"(d));
}
__device__ __forceinline__ unsigned s2u(const void* p) {
    unsigned a; asm("{ .reg .u64 t; cvta.to.shared.u64 t, %1; cvt.u32.u64 %0, t; }" : "=r"(a) : "l"(p)); return a;
}
__device__ __forceinline__ unsigned mapa_u(unsigned a, unsigned r) {
    unsigned o; asm("mapa.shared::cluster.u32 %0, %1, %2;" : "=r"(o) : "r"(a), "r"(r)); return o;
}
__device__ __forceinline__ void mbar_init(unsigned a, unsigned c) {
    asm volatile("mbarrier.init.shared.b64 [%0], %1;" :: "r"(a), "r"(c) : "memory");
}
__device__ __forceinline__ void mbar_wait_clu(unsigned a, unsigned ph) {
    asm volatile(
        "{\n\t.reg .pred P;\n"
        "W%=:\n\tmbarrier.try_wait.parity.acquire.cluster.shared::cta.b64 P, [%0], %1, 0x989680;\n"
        "\t@P bra D%=;\n\tbra W%=;\nD%=:\n\t}"
        :: "r"(a), "r"(ph) : "memory");
}
// RELAXED remote arrive: wake hint; tags carry data validity, bar carries WAR proof
__device__ __forceinline__ void mbar_arrive_rlx(unsigned a) {
    asm volatile("mbarrier.arrive.relaxed.cluster.shared::cluster.b64 _, [%0];" :: "r"(a) : "memory");
}
__device__ __forceinline__ void lds128(uint4& q, unsigned a) {
    asm volatile("ld.shared.v4.u32 {%0,%1,%2,%3}, [%4];"
                 : "=r"(q.x), "=r"(q.y), "=r"(q.z), "=r"(q.w) : "r"(a));
}

// ---------------- dummy (profiling slot alignment) ----------------
__global__ void dummy_k() {}

// ---------------- embedding gather ----------------
__global__ void embed_k(const int* __restrict__ wi, const int* __restrict__ ti,
                        const float* __restrict__ we, const float* __restrict__ te)
{
    int t = blockIdx.x, tid = threadIdx.x;
    const float* wr = we + (size_t)wi[t] * 300;
    for (int k = tid; k < 300; k += 128) g_x0[t * 400 + k] = wr[k];
    const float* tr = te + (size_t)ti[t] * 100;
    if (tid < 100) g_x0[t * 400 + 300 + tid] = tr[tid];
}

// ---------------- xi GEMM: k-major smem, vectorized inner loads ----------------
__global__ void __launch_bounds__(256) gemm_k(int layer,
        const float* __restrict__ W, const float* __restrict__ bih, const float* __restrict__ bhh)
{
    const int K = layer ? 800 : 400;
    const float* A = layer ? g_H0 : g_x0;
    int dir = blockIdx.z;
    int n0 = blockIdx.x * 64, m0 = blockIdx.y * 64;
    const float* Bp = W + (size_t)dir * GATES * K;

    __shared__ float As[16][72];
    __shared__ float Bs[16][72];
    int tid = threadIdx.x;
    int lr = tid >> 2, lc = (tid & 3) * 4;
    int tx = tid & 15, ty = tid >> 4;
    float acc[4][4] = {};

    for (int kt = 0; kt < K; kt += 16) {
        float4 av = *(const float4*)(A + (size_t)(m0 + lr) * K + kt + lc);
        float4 bv = *(const float4*)(Bp + (size_t)(n0 + lr) * K + kt + lc);
        __syncthreads();
        As[lc + 0][lr] = av.x; As[lc + 1][lr] = av.y; As[lc + 2][lr] = av.z; As[lc + 3][lr] = av.w;
        Bs[lc + 0][lr] = bv.x; Bs[lc + 1][lr] = bv.y; Bs[lc + 2][lr] = bv.z; Bs[lc + 3][lr] = bv.w;
        __syncthreads();
#pragma unroll
        for (int kk = 0; kk < 16; ++kk) {
            float4 a4 = *(const float4*)&As[kk][ty * 4];
            float4 b4 = *(const float4*)&Bs[kk][tx * 4];
            acc[0][0] += a4.x * b4.x; acc[0][1] += a4.x * b4.y;
            acc[0][2] += a4.x * b4.z; acc[0][3] += a4.x * b4.w;
            acc[1][0] += a4.y * b4.x; acc[1][1] += a4.y * b4.y;
            acc[1][2] += a4.y * b4.z; acc[1][3] += a4.y * b4.w;
            acc[2][0] += a4.z * b4.x; acc[2][1] += a4.z * b4.y;
            acc[2][2] += a4.z * b4.z; acc[2][3] += a4.z * b4.w;
            acc[3][0] += a4.w * b4.x; acc[3][1] += a4.w * b4.y;
            acc[3][2] += a4.w * b4.z; acc[3][3] += a4.w * b4.w;
        }
    }
#pragma unroll
    for (int jj = 0; jj < 4; ++jj) {
        int n = n0 + tx * 4 + jj;
        float bias = bih[dir * GATES + n] + bhh[dir * GATES + n];
        int gate = n / 400;
        int unit = n - gate * 400;
        int r2 = unit / 25, uw = unit % 25;
        int wp = uw >> 1, un = uw & 1;
        int jq = un * 4 + gate;
#pragma unroll
        for (int i = 0; i < 4; ++i) {
            int m = m0 + ty * 4 + i;
            size_t o = (((size_t)(dir * LQ + m)) * CLUST + r2) * 112 + wp * 8 + jq;
            g_xp[o] = acc[i][jj] + bias;
        }
    }
}

// ---------------- cluster LSTM scan: tagged atoms + post-read bar + early arrives ----------------
__global__ void __launch_bounds__(THREADS, 1) __cluster_dims__(CLUST, 1, 1)
scan_k(int layer, const float* __restrict__ Whh)
{
    // h_tag[parity 2][rank 16][slot 28] : u64 = {lo: f32 h, hi: u32 tag}
    __shared__ __align__(16) unsigned long long h_tag[2 * 448];
    __shared__ __align__(8)  unsigned long long mb[2];   // full0 full1 (count 16 each)

    int dir = blockIdx.x >> 4;
    unsigned rank; asm("mov.u32 %0, %%cluster_ctarank;" : "=r"(rank));
    int w = threadIdx.x >> 5, ld = threadIdx.x & 31;

    unsigned hb = s2u(h_tag), mbb = s2u(mb);

    if (threadIdx.x == 0) { mbar_init(mbb + 0, 16); mbar_init(mbb + 8, 16); }
    for (int i = threadIdx.x; i < 2 * 448; i += THREADS) {
        int q = i % 28;
        h_tag[i] = (q >= UPC) ? 0xFFFFFFFF00000000ULL : 0ULL;   // pads always pass
    }

    // ---- register-resident recurrent weights, mapped to PADDED (28/rank) slot layout ----
    unsigned long long wt[2][4][7];
    int uA = 2 * w, uB = 2 * w + 1;
    bool vB = (uB < UPC);
    int guA = rank * UPC + uA;
    int guB = rank * UPC + (vB ? uB : uA);
#pragma unroll
    for (int u = 0; u < 2; ++u) {
        bool vu = u ? vB : true;
        int gu = u ? guB : guA;
#pragma unroll
        for (int g = 0; g < 4; ++g) {
            const float* row = Whh + ((size_t)(dir * GATES + g * HID + gu)) * HID;
#pragma unroll
            for (int kk = 0; kk < 7; ++kk) {
                int m = 2 * ld + 64 * kk;
                int r = m / 28, q = m % 28;
                float lo = 0.f, hi = 0.f;
                if (vu && q < UPC)     lo = row[r * UPC + q];
                if (vu && q + 1 < UPC) hi = row[r * UPC + q + 1];
                wt[u][g][kk] = pk2(lo, hi);
            }
        }
    }

    // ---- per-lane remote store address: lane -> dst rank ld>>1, own unit lu=2w+(ld&1) ----
    int usel = ld & 1;
    int lu = 2 * w + usel;
    bool st_valid = (lu < UPC);
    unsigned st_base = mapa_u(hb, (unsigned)(ld >> 1)) + (unsigned)((rank * 28 + lu) * 8);

    // ---- warp0 remote arrive addresses: lane ld<16 -> rank ld ----
    unsigned rmb = mapa_u(mbb, (unsigned)(ld & 15));

    // ---- xi pointer: lane value j = (ld>>2)&7 ----
    int j = (ld >> 2) & 7;
    const float* xptr = g_xp + ((size_t)dir * LQ * CLUST + rank) * 112 + w * 8 + j;

    float* Hout = layer ? g_H1 : g_H0;
    float cA = 0.f, cB = 0.f;
    bool b4 = (ld & 16), b3 = (ld & 8), b2 = (ld & 4);
    unsigned ph0 = 0, ph1 = 0;

    asm volatile("barrier.cluster.arrive.aligned;" ::: "memory");
    asm volatile("barrier.cluster.wait.aligned;"  ::: "memory");

    for (int s = 0; s < LQ; ++s) {
        int t = dir ? (LQ - 1 - s) : s;
        float xig = __ldg(xptr + (size_t)t * (CLUST * 112));
        int b = s & 1;

        float v[8];
        if (s > 0) {
            int bp = b ^ 1;                       // buffer holding h_{s-1}
            if (bp) { mbar_wait_clu(mbb + 8, ph1); ph1 ^= 1; }
            else    { mbar_wait_clu(mbb + 0, ph0); ph0 ^= 1; }

            // load {h,tag} pairs; per-lane exit (warp reconverges at loop end)
            unsigned rbase = hb + (unsigned)(bp * 3584 + ld * 16);
            unsigned tgt = (unsigned)s;
            uint4 q0, q1, q2, q3, q4, q5, q6;
            for (;;) {
                lds128(q0, rbase);
                lds128(q1, rbase + 512);
                lds128(q2, rbase + 1024);
                lds128(q3, rbase + 1536);
                lds128(q4, rbase + 2048);
                lds128(q5, rbase + 2560);
                lds128(q6, rbase + 3072);
                bool ok = (q0.y >= tgt) & (q0.w >= tgt) & (q1.y >= tgt) & (q1.w >= tgt)
                        & (q2.y >= tgt) & (q2.w >= tgt) & (q3.y >= tgt) & (q3.w >= tgt)
                        & (q4.y >= tgt) & (q4.w >= tgt) & (q5.y >= tgt) & (q5.w >= tgt)
                        & (q6.y >= tgt) & (q6.w >= tgt);
                if (ok) break;
            }
            // READ-COMPLETE certification: all warps' reads of buffer bp are done
            // at this bar (low skew: everyone just passed the same flip + tags).
            __syncthreads();

            unsigned long long acc[2][4] = {};
#pragma unroll
            for (int kk = 0; kk < 7; ++kk) {
                uint4 qq = (kk == 0) ? q0 : (kk == 1) ? q1 : (kk == 2) ? q2 :
                           (kk == 3) ? q3 : (kk == 4) ? q4 : (kk == 5) ? q5 : q6;
                unsigned long long hv = pk2(__uint_as_float(qq.x), __uint_as_float(qq.z));
                fma2(acc[0][0], wt[0][0][kk], hv);
                fma2(acc[0][1], wt[0][1][kk], hv);
                fma2(acc[0][2], wt[0][2][kk], hv);
                fma2(acc[0][3], wt[0][3][kk], hv);
                fma2(acc[1][0], wt[1][0][kk], hv);
                fma2(acc[1][1], wt[1][1][kk], hv);
                fma2(acc[1][2], wt[1][2][kk], hv);
                fma2(acc[1][3], wt[1][3][kk], hv);
            }
#pragma unroll
            for (int u = 0; u < 2; ++u)
#pragma unroll
                for (int g = 0; g < 4; ++g) {
                    float lo, hi; upk2(acc[u][g], lo, hi);
                    v[u * 4 + g] = lo + hi;
                }
        } else {
            __syncthreads();                      // uniform bar at s=0 (no reads)
#pragma unroll
            for (int q = 0; q < 8; ++q) v[q] = 0.f;
        }

        // value-merging butterfly: value j lands in lanes with (ld>>2)&7 == j
        float wv[4];
#pragma unroll
        for (int k = 0; k < 4; ++k) {
            float keep = b4 ? v[k + 4] : v[k];
            float send = b4 ? v[k] : v[k + 4];
            wv[k] = keep + __shfl_xor_sync(0xffffffffu, send, 16);
        }
        float uv[2];
#pragma unroll
        for (int k = 0; k < 2; ++k) {
            float keep = b3 ? wv[k + 2] : wv[k];
            float send = b3 ? wv[k] : wv[k + 2];
            uv[k] = keep + __shfl_xor_sync(0xffffffffu, send, 8);
        }
        float z;
        {
            float keep = b2 ? uv[1] : uv[0];
            float send = b2 ? uv[0] : uv[1];
            z = keep + __shfl_xor_sync(0xffffffffu, send, 4);
        }
        z += __shfl_xor_sync(0xffffffffu, z, 2);
        z += __shfl_xor_sync(0xffffffffu, z, 1);

        // lane-parallel nonlinearity
        int gate = j & 3;
        float x = z + xig;
        float sarg = (gate == 2) ? 2.f * x : x;
        float e = __expf(-sarg);
        float rr = __fdividef(1.f, 1.f + e);
        float y = (gate == 2) ? (2.f * rr - 1.f) : rr;

        float iA = __shfl_sync(0xffffffffu, y, 0);
        float fA = __shfl_sync(0xffffffffu, y, 4);
        float gA = __shfl_sync(0xffffffffu, y, 8);
        float oA = __shfl_sync(0xffffffffu, y, 12);
        float iB = __shfl_sync(0xffffffffu, y, 16);
        float fB = __shfl_sync(0xffffffffu, y, 20);
        float gB = __shfl_sync(0xffffffffu, y, 24);
        float oB = __shfl_sync(0xffffffffu, y, 28);
        cA = fA * cA + iA * gA;
        cB = fB * cB + iB * gB;

        float xc = usel ? cB : cA;
        float ec = __expf(-2.f * xc);
        float tc = __fdividef(2.f, 1.f + ec) - 1.f;
        float tA = __shfl_sync(0xffffffffu, tc, 0);
        float tB = __shfl_sync(0xffffffffu, tc, 1);
        float hA = oA * tA, hB = oB * tB;

        // gmem h output (R4 ordering: before broadcast)
        if (ld == 0) {
            float* o = Hout + (size_t)t * 800 + dir * HID;
            o[guA] = hA;
            if (vB) o[guB] = hB;
        }

        if (s < LQ - 1) {
            // broadcast {h, tag=s+1} atoms via per-lane scattered remote stores
            if (st_valid) {
                unsigned long long pay = ((unsigned long long)(unsigned)(s + 1) << 32) |
                                         (unsigned long long)__float_as_uint(usel ? hB : hA);
                asm volatile("st.shared::cluster.u64 [%0], %1;"
                             :: "r"(st_base + (unsigned)(b * 3584)), "l"(pay) : "memory");
            }
            // EARLY arrives: warp 0 fires wake hints right after its own stores.
            // The post-read bar above already certified whole-CTA reads (WAR);
            // lagging warps' stores are covered by consumers' tag checks.
            if (w == 0 && ld < 16) mbar_arrive_rlx(rmb + (unsigned)(b * 8));
        }
    }

    asm volatile("barrier.cluster.arrive.aligned;" ::: "memory");
    asm volatile("barrier.cluster.wait.aligned;"  ::: "memory");
}

// ---------------- head/dep projections ----------------
__global__ void headdep_k(const float* __restrict__ fw)
{
    int i = blockIdx.x;
    const float* hr = g_H1 + (size_t)i * 800;
    float a = 0.f, b = 0.f;
    for (int k = threadIdx.x; k < 800; k += 256) {
        float h = hr[k];
        a += h * __ldg(fw + k);
        b += h * __ldg(fw + 800 + k);
    }
#pragma unroll
    for (int o = 16; o; o >>= 1) {
        a += __shfl_xor_sync(0xffffffffu, a, o);
        b += __shfl_xor_sync(0xffffffffu, b, o);
    }
    __shared__ float sa[8], sb2[8];
    int w = threadIdx.x >> 5, ld = threadIdx.x & 31;
    if (ld == 0) { sa[w] = a; sb2[w] = b; }
    __syncthreads();
    if (threadIdx.x == 0) {
        float A = 0.f, B = 0.f;
#pragma unroll
        for (int q = 0; q < 8; ++q) { A += sa[q]; B += sb2[q]; }
        g_sv[i] = A; g_tv[i] = B;
    }
}

// ---------------- pairwise scores ----------------
__global__ void scores_k(const float* __restrict__ fb, float* __restrict__ out)
{
    int i = blockIdx.x, jj = threadIdx.x;
    out[(size_t)i * LQ + jj] = tanhf(g_sv[i] + g_tv[jj] + fb[0]);
}

// ---------------- launch ----------------
extern "C" void kernel_launch(void* const* d_in, const int* in_sizes, int n_in,
                              void* d_out, int out_size)
{
    int base = (in_sizes[2] == 1) ? 3 : 2;
    const int*   wi   = (const int*)d_in[0];
    const int*   ti   = (const int*)d_in[1];
    const float* we   = (const float*)d_in[base + 0];
    const float* te   = (const float*)d_in[base + 1];
    const float* wih0 = (const float*)d_in[base + 2];
    const float* whh0 = (const float*)d_in[base + 3];
    const float* bih0 = (const float*)d_in[base + 4];
    const float* bhh0 = (const float*)d_in[base + 5];
    const float* wih1 = (const float*)d_in[base + 6];
    const float* whh1 = (const float*)d_in[base + 7];
    const float* bih1 = (const float*)d_in[base + 8];
    const float* bhh1 = (const float*)d_in[base + 9];
    const float* fw   = (const float*)d_in[base + 10];
    const float* fb   = (const float*)d_in[base + 11];
    float* out = (float*)d_out;

    cudaFuncSetAttribute(scan_k, cudaFuncAttributeNonPortableClusterSizeAllowed, 1);

    embed_k<<<LQ, 128>>>(wi, ti, we, te);
    dim3 gg(GATES / 64, LQ / 64, 2);
    gemm_k<<<gg, 256>>>(0, wih0, bih0, bhh0);
    dummy_k<<<1, 32>>>();                          // keeps scan_k at ncu capture slot 5
    scan_k<<<2 * CLUST, THREADS>>>(0, whh0);
    gemm_k<<<gg, 256>>>(1, wih1, bih1, bhh1);
    scan_k<<<2 * CLUST, THREADS>>>(1, whh1);
    headdep_k<<<LQ, 256>>>(fw);
    scores_k<<<LQ, LQ>>>(fb, out);
}